// round 2
// baseline (speedup 1.0000x reference)
#include <cuda_runtime.h>
#include <math.h>

// ---------------- problem constants ----------------
#define VIEWS 512
#define DETS  512
#define H_IMG 256
#define W_IMG 256

__device__ __constant__ float kD_IMG = 0.006641f;
// VIRDET = D_DET * S2R / (S2R + D2R) = 0.0072*5.95/10.856
#define S2R_F 5.95f
#define VIRDET_D (0.0072 * 5.95 / (5.95 + 4.906))
__device__ __constant__ float kINV_VIRDET = (float)(1.0 / VIRDET_D);
#define D_ANG_F ((float)(2.0 * 3.14159265358979323846 / 512.0))

// Scratch: filtered sinogram, layout [b*VIEWS + v][DETS]  (2 MB)
__device__ float g_pf[2 * VIEWS * DETS];

// ---------------- kernel 1: weighted ramp filter ----------------
// One block per (b, view) row. out[j] = sum_m pin[j+m-511]*filt[m]
// filt is symmetric with zeros at even |x|>0, so fold:
// out[j] = filt[511]*pin[j] + sum_{i=0..255, o=2i+1} filt[511+o]*(pin[j-o]+pin[j+o])
__global__ __launch_bounds__(DETS) void filter_kernel(
    const float* __restrict__ proj,   // [2,1,VIEWS,DETS]
    const float* __restrict__ w,      // [DETS]
    const float* __restrict__ filt)   // [2*DETS-1] = 1023
{
    __shared__ float sp[DETS + 2 * (DETS - 1)];  // 1534, zero-padded window
    __shared__ float sf[DETS / 2];               // odd-tap coefficients

    const int row = blockIdx.x;       // b*VIEWS + v
    const int j   = threadIdx.x;      // 0..511

    // zero pads: indices [0,511) and [1023,1534) -- 511 elements each.
    if (j < DETS - 1) {
        sp[j] = 0.0f;
        sp[2 * DETS - 1 + j] = 0.0f;  // 1023 + j, j in [0,511) -> 1023..1533
    }
    // center: weighted projection
    sp[DETS - 1 + j] = proj[row * DETS + j] * w[j];
    if (j < DETS / 2) sf[j] = filt[DETS + 2 * j];   // filt[512 + 2i] = f(o=2i+1)
    const float c0 = filt[DETS - 1];                // f(0)
    __syncthreads();

    const float* c = sp + (DETS - 1) + j;
    float acc = c0 * c[0];
#pragma unroll 8
    for (int i = 0; i < DETS / 2; ++i) {
        const int o = 2 * i + 1;
        acc = fmaf(sf[i], c[-o] + c[o], acc);
    }
    g_pf[row * DETS + j] = acc;
}

// ---------------- kernel 2: per-view backprojection ----------------
// grid = (VIEWS, H_IMG/ROWS), block = W_IMG threads (x). 16 rows per block.
#define ROWS_PER_BLK 16

__global__ __launch_bounds__(W_IMG) void bp_kernel(float* __restrict__ out)
{
    __shared__ float s0[DETS];
    __shared__ float s1[DETS];

    const int v     = blockIdx.x;
    const int ytile = blockIdx.y;
    const int x     = threadIdx.x;

    // stage this view's filtered rows (both batches) into shared
    s0[x]          = g_pf[v * DETS + x];
    s0[x + W_IMG]  = g_pf[v * DETS + x + W_IMG];
    s1[x]          = g_pf[(VIEWS + v) * DETS + x];
    s1[x + W_IMG]  = g_pf[(VIEWS + v) * DETS + x + W_IMG];

    const float beta = v * D_ANG_F;
    const float cb = cosf(beta);
    const float sb = sinf(beta);
    const float xs  = (x - (W_IMG - 1) * 0.5f) * kD_IMG;
    const float xcb = xs * cb;
    const float xsb = xs * sb;
    __syncthreads();

    float* o0 = out + (size_t)v * (H_IMG * W_IMG)
                    + (size_t)ytile * ROWS_PER_BLK * W_IMG + x;
    float* o1 = o0 + (size_t)VIEWS * H_IMG * W_IMG;

#pragma unroll
    for (int r = 0; r < ROWS_PER_BLK; ++r) {
        const int   y  = ytile * ROWS_PER_BLK + r;
        const float ys = ((H_IMG - 1) * 0.5f - y) * kD_IMG;

        const float d    = S2R_F - (xcb + ys * sb);
        const float invd = 1.0f / d;
        const float u    = S2R_F * (ys * cb - xsb) * invd;
        const float sw   = S2R_F * invd;
        const float wgt  = sw * sw;

        const float t  = u * kINV_VIRDET + (DETS - 1) * 0.5f;
        const float f0 = floorf(t);
        const int   i0 = (int)f0;
        const float fr = t - f0;

        const float w0 = (i0 >= 0  && i0 < DETS)     ? (1.0f - fr) : 0.0f;
        const float w1 = (i0 >= -1 && i0 < DETS - 1) ? fr          : 0.0f;
        const int i0c = min(max(i0, 0), DETS - 1);
        const int i1c = min(max(i0 + 1, 0), DETS - 1);

        o0[r * W_IMG] = wgt * (s0[i0c] * w0 + s0[i1c] * w1);
        o1[r * W_IMG] = wgt * (s1[i0c] * w0 + s1[i1c] * w1);
    }
}

// ---------------- launcher ----------------
extern "C" void kernel_launch(void* const* d_in, const int* in_sizes, int n_in,
                              void* d_out, int out_size)
{
    const float* proj = (const float*)d_in[0];   // 2*1*512*512
    const float* w    = (const float*)d_in[1];   // 512
    const float* filt = (const float*)d_in[2];   // 1023
    float* out = (float*)d_out;                  // 2*512*256*256

    filter_kernel<<<2 * VIEWS, DETS>>>(proj, w, filt);
    bp_kernel<<<dim3(VIEWS, H_IMG / ROWS_PER_BLK), W_IMG>>>(out);
    (void)in_sizes; (void)n_in; (void)out_size;
}

// round 3
// speedup vs baseline: 1.6010x; 1.6010x over previous
#include <cuda_runtime.h>
#include <math.h>

#define VIEWS 512
#define DETS  512
#define H_IMG 256
#define W_IMG 256

#define DIMG_F  0.006641f
#define S2R_F   5.95f
#define VIRDET_D (0.0072 * 5.95 / (5.95 + 4.906))
#define INVVIR_F ((float)(1.0 / VIRDET_D))
#define D_ANG_F ((float)(2.0 * 3.14159265358979323846 / 512.0))

// filtered sinogram scratch: [b*VIEWS + v][DETS]
__device__ float g_pf[2 * VIEWS * DETS];

// ============================================================================
// Kernel 1: weighted ramp filter, register-blocked.
// out[j] = f0*S[511+j] + sum_{i=0..255} f_odd[i]*(S[511+j-o] + S[511+j+o]),
// o = 2i+1, S = zero-padded weighted row (padded index X in [0,1534)).
// Row stored bit-transposed in smem: S[X] -> spT[(X&7)*193 + (X>>3)].
// Block = 64 threads, each computes 8 consecutive outputs (j0 = 8*tid).
// Taps processed in chunks of 8: thread keeps 22-value L/R windows in regs.
//   left  X = 8*(tid - 2c + 62) + t , tap kk / output o uses t = o + 14 - 2kk
//   right X = 8*(tid + 2c + 64) + t , tap kk / output o uses t = o + 2kk
// ============================================================================
__global__ __launch_bounds__(64) void filter_kernel(
    const float* __restrict__ proj,   // [2,1,VIEWS,DETS]
    const float* __restrict__ w,      // [DETS]
    const float* __restrict__ filt)   // [2*DETS-1]
{
    __shared__ float spT[8 * 193];    // 1544 floats
    __shared__ float sf[256];

    const int row = blockIdx.x;       // b*VIEWS + v
    const int tid = threadIdx.x;      // 0..63

    for (int X = tid; X < 1534; X += 64) {
        float val = 0.0f;
        if (X >= 511 && X < 1023) {
            const int j = X - 511;
            val = proj[row * DETS + j] * w[j];
        }
        spT[(X & 7) * 193 + (X >> 3)] = val;
    }
    for (int t = tid; t < 256; t += 64) sf[t] = filt[512 + 2 * t];
    __syncthreads();

    float acc[8];
    {
        const float c0 = filt[511];
#pragma unroll
        for (int k = 0; k < 8; ++k) {
            const int q = 7 + k;      // X = 8*(tid+63) + q
            acc[k] = c0 * spT[(q & 7) * 193 + (tid + 63 + (q >> 3))];
        }
    }

#pragma unroll 1
    for (int c = 0; c < 32; ++c) {
        const int baseL = tid - 2 * c + 62;
        const int baseR = tid + 2 * c + 64;
        float L[22], R[22];
#pragma unroll
        for (int t = 0; t < 22; ++t) {
            L[t] = spT[(t & 7) * 193 + (baseL + (t >> 3))];
            R[t] = spT[(t & 7) * 193 + (baseR + (t >> 3))];
        }
#pragma unroll
        for (int kk = 0; kk < 8; ++kk) {
            const float f = sf[8 * c + kk];
#pragma unroll
            for (int o = 0; o < 8; ++o)
                acc[o] = fmaf(f, L[o + 14 - 2 * kk] + R[o + 2 * kk], acc[o]);
        }
    }

    float4* outp = (float4*)&g_pf[row * DETS + tid * 8];
    outp[0] = make_float4(acc[0], acc[1], acc[2], acc[3]);
    outp[1] = make_float4(acc[4], acc[5], acc[6], acc[7]);
}

// ============================================================================
// Kernel 2: per-view backprojection.
// grid = (VIEWS, H_IMG/RPB), block = 256 threads (one column x each).
// Detector row (both batches) staged as float2 with 2-zero guard pads so
// out-of-range interpolation needs only one clamp, no predicates.
// ============================================================================
#define RPB 32

__global__ __launch_bounds__(W_IMG) void bp_kernel(float* __restrict__ out)
{
    __shared__ float2 s01[516];       // logical det i at [i+2]; [0,1]=[514,515]=0

    const int v  = blockIdx.x;
    const int yt = blockIdx.y;
    const int x  = threadIdx.x;

    {
        const float a0 = g_pf[v * DETS + x];
        const float a1 = g_pf[(VIEWS + v) * DETS + x];
        const float b0 = g_pf[v * DETS + x + 256];
        const float b1 = g_pf[(VIEWS + v) * DETS + x + 256];
        s01[x + 2]   = make_float2(a0, a1);
        s01[x + 258] = make_float2(b0, b1);
        if (x < 2) {
            s01[x]       = make_float2(0.0f, 0.0f);
            s01[514 + x] = make_float2(0.0f, 0.0f);
        }
    }

    const float beta = v * D_ANG_F;
    const float cb = cosf(beta);
    const float sb = sinf(beta);
    const float xs  = (x - (W_IMG - 1) * 0.5f) * DIMG_F;
    const float ys0 = ((H_IMG - 1) * 0.5f - yt * RPB) * DIMG_F;

    const float d0 = S2R_F - xs * cb - ys0 * sb;
    const float dd = DIMG_F * sb;                 // d_r = d0 + r*dd
    const float AF = S2R_F * INVVIR_F;
    const float n0 = (ys0 * cb - xs * sb) * AF;
    const float dn = DIMG_F * cb * AF;            // n_r = n0 - r*dn
    __syncthreads();

    float* o0 = out + ((size_t)v * H_IMG + yt * RPB) * W_IMG + x;
    float* o1 = o0 + (size_t)VIEWS * H_IMG * W_IMG;

#pragma unroll
    for (int r = 0; r < RPB; ++r) {
        const float rf = (float)r;
        const float d  = fmaf(rf, dd, d0);
        float invd;
        asm("rcp.approx.f32 %0, %1;" : "=f"(invd) : "f"(d));
        const float nA = fmaf(rf, -dn, n0);
        const float t  = fmaf(nA, invd, (DETS - 1) * 0.5f);
        const float tf = floorf(t);
        const float fr = t - tf;
        const int   i0 = (int)tf;
        const int   ip = min(max(i0 + 2, 0), 514);

        const float2 va = s01[ip];
        const float2 vb = s01[ip + 1];

        const float sw  = S2R_F * invd;
        const float wgt = sw * sw;

        o0[r * W_IMG] = wgt * fmaf(fr, vb.x - va.x, va.x);
        o1[r * W_IMG] = wgt * fmaf(fr, vb.y - va.y, va.y);
    }
}

// ---------------- launcher ----------------
extern "C" void kernel_launch(void* const* d_in, const int* in_sizes, int n_in,
                              void* d_out, int out_size)
{
    const float* proj = (const float*)d_in[0];   // 2*1*512*512
    const float* w    = (const float*)d_in[1];   // 512
    const float* filt = (const float*)d_in[2];   // 1023
    float* out = (float*)d_out;                  // 2*512*256*256

    filter_kernel<<<2 * VIEWS, 64>>>(proj, w, filt);
    bp_kernel<<<dim3(VIEWS, H_IMG / RPB), W_IMG>>>(out);
    (void)in_sizes; (void)n_in; (void)out_size;
}

// round 5
// speedup vs baseline: 1.7720x; 1.1068x over previous
#include <cuda_runtime.h>
#include <math.h>

#define VIEWS 512
#define DETS  512
#define H_IMG 256
#define W_IMG 256

#define DIMG_F  0.006641f
#define S2R_F   5.95f
#define VIRDET_D (0.0072 * 5.95 / (5.95 + 4.906))
#define INVVIR_F ((float)(1.0 / VIRDET_D))
#define D_ANG_F ((float)(2.0 * 3.14159265358979323846 / 512.0))

// filtered sinogram scratch, batch-packed: [v][det] -> (b0, b1)   (2 MB)
__device__ float2 g_pf2[VIEWS * DETS];

// ---- packed f32x2 helpers (Blackwell FFMA2/FADD2, PTX-only) ----
union F2U { float2 f; unsigned long long u; };
__device__ __forceinline__ float2 fma2(float2 a, float2 b, float2 c) {
    F2U A, B, C, D; A.f = a; B.f = b; C.f = c;
    asm("fma.rn.f32x2 %0, %1, %2, %3;" : "=l"(D.u) : "l"(A.u), "l"(B.u), "l"(C.u));
    return D.f;
}
__device__ __forceinline__ float2 add2(float2 a, float2 b) {
    F2U A, B, D; A.f = a; B.f = b;
    asm("add.rn.f32x2 %0, %1, %2;" : "=l"(D.u) : "l"(A.u), "l"(B.u));
    return D.f;
}

// ============================================================================
// Kernel 1: weighted ramp filter, register-blocked, both batches packed f32x2.
// out[j] = f0*S[511+j] + sum_{i=0..255} f_odd[i]*(S[511+j-o] + S[511+j+o]),
// o = 2i+1.  S = zero-padded weighted row pair (padded index X in [0,1534)).
// Bit-transposed smem: S[X] -> spT[(X&7)*193 + (X>>3)]  (float2 elements).
// Block = 64 threads = one view; each thread -> 8 outputs x 2 batches.
// Taps in chunks of 8, 22-value L/R windows held in registers:
//   left  X = 8*(tid - 2c + 62) + (o + 14 - 2kk)
//   right X = 8*(tid + 2c + 64) + (o + 2kk)
// ============================================================================
__global__ __launch_bounds__(64) void filter_kernel(
    const float* __restrict__ proj,   // [2,1,VIEWS,DETS]
    const float* __restrict__ w,      // [DETS]
    const float* __restrict__ filt)   // [2*DETS-1]
{
    __shared__ float2 spT[8 * 193];   // 1544 float2
    __shared__ float2 sf2[256];       // odd taps, duplicated in both lanes

    const int v   = blockIdx.x;       // view
    const int tid = threadIdx.x;      // 0..63

    for (int X = tid; X < 1534; X += 64) {
        float2 val = make_float2(0.0f, 0.0f);
        if (X >= 511 && X < 1023) {
            const int j = X - 511;
            const float wj = w[j];
            val.x = proj[v * DETS + j] * wj;
            val.y = proj[VIEWS * DETS + v * DETS + j] * wj;
        }
        spT[(X & 7) * 193 + (X >> 3)] = val;
    }
    for (int t = tid; t < 256; t += 64) {
        const float fv = filt[512 + 2 * t];
        sf2[t] = make_float2(fv, fv);
    }
    __syncthreads();

    float2 acc[8];
    {
        const float c0 = filt[511];
#pragma unroll
        for (int k = 0; k < 8; ++k) {
            const int q = 7 + k;      // X = 8*(tid+63) + q  ->  511 + (8*tid+k)
            const float2 s = spT[(q & 7) * 193 + (tid + 63 + (q >> 3))];
            acc[k] = make_float2(c0 * s.x, c0 * s.y);
        }
    }

#pragma unroll 1
    for (int c = 0; c < 32; ++c) {
        const int baseL = tid - 2 * c + 62;
        const int baseR = tid + 2 * c + 64;
        float2 L[22], R[22];
#pragma unroll
        for (int t = 0; t < 22; ++t) {
            L[t] = spT[(t & 7) * 193 + (baseL + (t >> 3))];
            R[t] = spT[(t & 7) * 193 + (baseR + (t >> 3))];
        }
#pragma unroll
        for (int kk = 0; kk < 8; ++kk) {
            const float2 f = sf2[8 * c + kk];
#pragma unroll
            for (int o = 0; o < 8; ++o)
                acc[o] = fma2(f, add2(L[o + 14 - 2 * kk], R[o + 2 * kk]), acc[o]);
        }
    }

    float4* outp = (float4*)&g_pf2[v * DETS + tid * 8];
#pragma unroll
    for (int k = 0; k < 4; ++k)
        outp[k] = make_float4(acc[2 * k].x,     acc[2 * k].y,
                              acc[2 * k + 1].x, acc[2 * k + 1].y);
}

// ============================================================================
// Kernel 2: per-view backprojection.
// grid = (VIEWS, H_IMG/RPB), block = 256 (one column x each), 32 rows/block.
// Detector row pair staged as float2 with 2-zero guard pads: out-of-range
// interpolation needs only one clamp, no predicates. Streaming stores.
// ============================================================================
#define RPB 32

__global__ __launch_bounds__(W_IMG) void bp_kernel(float* __restrict__ out)
{
    __shared__ float2 s01[516];       // det i at [i+2]; [0,1],[514,515] = 0

    const int v  = blockIdx.x;
    const int yt = blockIdx.y;
    const int x  = threadIdx.x;

    s01[x + 2]   = g_pf2[v * DETS + x];
    s01[x + 258] = g_pf2[v * DETS + x + 256];
    if (x < 2) {
        s01[x]       = make_float2(0.0f, 0.0f);
        s01[514 + x] = make_float2(0.0f, 0.0f);
    }

    const float beta = v * D_ANG_F;
    const float cb = cosf(beta);
    const float sb = sinf(beta);
    const float xs  = (x - (W_IMG - 1) * 0.5f) * DIMG_F;
    const float ys0 = ((H_IMG - 1) * 0.5f - yt * RPB) * DIMG_F;

    const float d0 = S2R_F - xs * cb - ys0 * sb;
    const float dd = DIMG_F * sb;                 // d_r = d0 + r*dd
    const float AF = S2R_F * INVVIR_F;
    const float n0 = (ys0 * cb - xs * sb) * AF;
    const float dn = DIMG_F * cb * AF;            // n_r = n0 - r*dn
    __syncthreads();

    float* o0 = out + ((size_t)v * H_IMG + yt * RPB) * W_IMG + x;
    float* o1 = o0 + (size_t)VIEWS * H_IMG * W_IMG;

#pragma unroll
    for (int r = 0; r < RPB; ++r) {
        const float rf = (float)r;
        const float d  = fmaf(rf, dd, d0);
        float invd;
        asm("rcp.approx.f32 %0, %1;" : "=f"(invd) : "f"(d));
        const float nA = fmaf(rf, -dn, n0);
        const float t  = fmaf(nA, invd, (DETS - 1) * 0.5f);
        const float tf = floorf(t);
        const float fr = t - tf;
        const int   i0 = (int)tf;
        const int   ip = min(max(i0 + 2, 0), 514);

        const float2 va = s01[ip];
        const float2 vb = s01[ip + 1];

        const float sw  = S2R_F * invd;
        const float wgt = sw * sw;

        __stcs(&o0[r * W_IMG], wgt * fmaf(fr, vb.x - va.x, va.x));
        __stcs(&o1[r * W_IMG], wgt * fmaf(fr, vb.y - va.y, va.y));
    }
}

// ---------------- launcher ----------------
extern "C" void kernel_launch(void* const* d_in, const int* in_sizes, int n_in,
                              void* d_out, int out_size)
{
    const float* proj = (const float*)d_in[0];   // 2*1*512*512
    const float* w    = (const float*)d_in[1];   // 512
    const float* filt = (const float*)d_in[2];   // 1023
    float* out = (float*)d_out;                  // 2*512*256*256

    filter_kernel<<<VIEWS, 64>>>(proj, w, filt);
    bp_kernel<<<dim3(VIEWS, H_IMG / RPB), W_IMG>>>(out);
    (void)in_sizes; (void)n_in; (void)out_size;
}